// round 3
// baseline (speedup 1.0000x reference)
#include <cuda_runtime.h>

#define BATCH 4
#define HH 128
#define WW 128
#define CIN 64
#define CQK 8
#define NPX 8          // pixels per attn block (consecutive x)
#define PLANE (HH*WW)

// ---------------- scratch (device globals, no runtime alloc) ----------------
__device__ float g_q[BATCH*CQK*PLANE];            //   2 MB
__device__ float g_k[BATCH*CQK*PLANE];            //   2 MB
__device__ float g_v[BATCH*CIN*PLANE];            //  16.8 MB
__device__ float g_local[BATCH*PLANE*1600ll];     // 419 MB

// =====================================================================
// Kernel A: 1x1-conv projections q,k,v  (NHWC input -> NCHW scratch)
// block = one image row (128 threads, thread = x), weights in smem (broadcast)
// =====================================================================
__global__ void proj_kernel(const float* __restrict__ x,
                            const float* __restrict__ Wq, const float* __restrict__ bq,
                            const float* __restrict__ Wk, const float* __restrict__ bk,
                            const float* __restrict__ Wv, const float* __restrict__ bv)
{
    __shared__ float s_wq[512], s_wk[512], s_wv[4096], s_bq[8], s_bk[8], s_bv[64];
    int tid = threadIdx.x;
    for (int i = tid; i < 512; i += 128) { s_wq[i] = Wq[i]; s_wk[i] = Wk[i]; }
    for (int i = tid; i < 4096; i += 128) s_wv[i] = Wv[i];
    if (tid < 8)  { s_bq[tid] = bq[tid]; s_bk[tid] = bk[tid]; }
    if (tid < 64) { s_bv[tid] = bv[tid]; }
    __syncthreads();

    int b = blockIdx.x >> 7;
    int y = blockIdx.x & 127;
    int xcol = tid;
    long pix = ((long)(b*HH + y))*WW + xcol;

    float xv[64];
    const float4* xp = (const float4*)(x + pix*64);
#pragma unroll
    for (int c4 = 0; c4 < 16; c4++) {
        float4 t = xp[c4];
        xv[c4*4+0] = t.x; xv[c4*4+1] = t.y; xv[c4*4+2] = t.z; xv[c4*4+3] = t.w;
    }

    int base_qk = (b*CQK)*PLANE + y*WW + xcol;
#pragma unroll 1
    for (int o = 0; o < 8; o++) {
        float aq = s_bq[o], ak = s_bk[o];
#pragma unroll
        for (int c = 0; c < 64; c++) {
            aq += xv[c]*s_wq[o*64+c];
            ak += xv[c]*s_wk[o*64+c];
        }
        g_q[base_qk + o*PLANE] = aq;
        g_k[base_qk + o*PLANE] = ak;
    }
    int base_v = (b*CIN)*PLANE + y*WW + xcol;
#pragma unroll 1
    for (int o = 0; o < 64; o++) {
        float av = s_bv[o];
#pragma unroll
        for (int c = 0; c < 64; c++) av += xv[c]*s_wv[o*64+c];
        g_v[base_v + o*PLANE] = av;
    }
}

// =====================================================================
// Kernel B: per-pixel attention (logits -> softmax -> attn out -> local)
// block = 8 consecutive x pixels, 256 threads (1 warp / pixel for local)
// dynamic smem layout (floats):
//   s_vp   [0, 12800)      per-pixel unfolded v  (vp[p][g], g = unfold-flat)
//   s_att  [12800, 17800)  per-pixel logits/attn [p][625]
//   s_vt   [17800, 21640)  v halo tile [64][5][12]
//   s_qt   [21640, 22120)  q halo tile [8][5][12]
//   s_kt   [22120, 22600)  k halo tile
//   s_off  [22600, 22800)  int LUT: g<200 -> tile offset c*60+di*12+dj
// total 22800 floats = 91200 B
// =====================================================================
__global__ void attn_kernel(float* __restrict__ attn_out)
{
    extern __shared__ float sm[];
    float* s_vp  = sm;
    float* s_att = sm + 12800;
    float* s_vt  = sm + 17800;
    float* s_qt  = sm + 21640;
    float* s_kt  = sm + 22120;
    int*   s_off = (int*)(sm + 22600);

    int tid = threadIdx.x;
    int b  = blockIdx.x >> 11;          // 2048 blocks per batch
    int r  = blockIdx.x & 2047;
    int y  = r >> 4;
    int x0 = (r & 15) * NPX;

    // ---- stage halo tiles (zero-padded like unfold) ----
    for (int idx = tid; idx < 480; idx += 256) {
        int c = idx/60, r2 = idx%60, dy = r2/12, xx = r2%12;
        int gy = y + dy - 2, gx = x0 + xx - 2;
        float vq = 0.f, vk = 0.f;
        if (gy >= 0 && gy < HH && gx >= 0 && gx < WW) {
            int gi = ((b*CQK + c)*HH + gy)*WW + gx;
            vq = g_q[gi]; vk = g_k[gi];
        }
        s_qt[idx] = vq; s_kt[idx] = vk;
    }
    for (int idx = tid; idx < 3840; idx += 256) {
        int ch = idx/60, r2 = idx%60, dy = r2/12, xx = r2%12;
        int gy = y + dy - 2, gx = x0 + xx - 2;
        float vv = 0.f;
        if (gy >= 0 && gy < HH && gx >= 0 && gx < WW)
            vv = g_v[((b*CIN + ch)*HH + gy)*WW + gx];
        s_vt[idx] = vv;
    }
    for (int g = tid; g < 200; g += 256) {
        int c = g/25, ko = g%25;
        s_off[g] = c*60 + (ko/5)*12 + (ko%5);
    }
    __syncthreads();

    // ---- expand v tile into per-pixel unfold-flat vectors ----
    for (int g = tid; g < 1600; g += 256) {
        int ch = g/25, ko = g%25;
        int off = ch*60 + (ko/5)*12 + (ko%5);
#pragma unroll
        for (int p = 0; p < NPX; p++) s_vp[p*1600 + g] = s_vt[off + p];
    }

    // ---- logits: qp[n,cc]·kp[m,cc], qp flat index = n*8+cc (raw reshape) ----
    for (int idx = tid; idx < 5000; idx += 256) {
        int p = idx/625, e = idx - p*625;
        int n = e/25,    m = e - n*25;
        float acc = 0.f;
#pragma unroll
        for (int cc = 0; cc < 8; cc++)
            acc += s_qt[s_off[n*8+cc] + p] * s_kt[s_off[m*8+cc] + p];
        s_att[idx] = acc;
    }
    __syncthreads();

    // ---- softmax over m (200 rows of 25) ----
    if (tid < 200) {
        int p = tid/25, n = tid - (tid/25)*25;
        float* row = s_att + p*625 + n*25;
        float mx = row[0];
#pragma unroll
        for (int m = 1; m < 25; m++) mx = fmaxf(mx, row[m]);
        float e_[25]; float sum = 0.f;
#pragma unroll
        for (int m = 0; m < 25; m++) { e_[m] = __expf(row[m]-mx); sum += e_[m]; }
        float inv = 1.f/sum;
#pragma unroll
        for (int m = 0; m < 25; m++) row[m] = e_[m]*inv;
    }
    __syncthreads();

    // ---- write attn: 8 pixels -> one contiguous 5000-float region ----
    long pixb = ((long)(b*HH + y))*WW + x0;
    float* ag = attn_out + pixb*625;
    for (int idx = tid; idx < 5000; idx += 256) ag[idx] = s_att[idx];

    // ---- local = attn @ vp, warp p, lane l handles cc = l and l+32 ----
    {
        int p = tid >> 5, l = tid & 31;
        const float* vpp = s_vp + p*1600;
        const float* ap  = s_att + p*625;
        float* lg = g_local + (pixb + p)*1600;
#pragma unroll 1
        for (int nb = 0; nb < 5; nb++) {
            float a00=0,a01=0,a10=0,a11=0,a20=0,a21=0,a30=0,a31=0,a40=0,a41=0;
            const float* arow = ap + nb*125;
#pragma unroll 5
            for (int m = 0; m < 25; m++) {
                float v1 = vpp[m*64 + l];        // bank = lane: conflict-free
                float v2 = vpp[m*64 + 32 + l];
                float t0 = arow[m];        a00 += t0*v1; a01 += t0*v2;
                float t1 = arow[25 + m];   a10 += t1*v1; a11 += t1*v2;
                float t2 = arow[50 + m];   a20 += t2*v1; a21 += t2*v2;
                float t3 = arow[75 + m];   a30 += t3*v1; a31 += t3*v2;
                float t4 = arow[100 + m];  a40 += t4*v1; a41 += t4*v2;
            }
            float* o = lg + nb*320;
            o[l]       = a00; o[32+l]  = a01;
            o[64+l]    = a10; o[96+l]  = a11;
            o[128+l]   = a20; o[160+l] = a21;
            o[192+l]   = a30; o[224+l] = a31;
            o[256+l]   = a40; o[288+l] = a41;
        }
    }
}

// =====================================================================
// Kernel C: fold (pure gather) + gamma*folded + x, NHWC output
// block = 8 output pixels x 64 channels (512 threads, c fastest -> coalesced)
// =====================================================================
__global__ void fold_kernel(const float* __restrict__ x,
                            const float* __restrict__ gamma,
                            float* __restrict__ outp)
{
    int tid = threadIdx.x;
    int c  = tid & 63;
    int xi = tid >> 6;
    int b  = blockIdx.x >> 11;
    int r  = blockIdx.x & 2047;
    int Y  = r >> 4;
    int X  = (r & 15)*8 + xi;

    float acc = 0.f;
    int rowbase = c*25;
#pragma unroll
    for (int i = 0; i < 5; i++) {
        int sy = Y + 2 - i;
        if (sy < 0 || sy >= HH) continue;
        long pb = ((long)(b*HH + sy))*WW;
#pragma unroll
        for (int j = 0; j < 5; j++) {
            int sx = X + 2 - j;
            if (sx < 0 || sx >= WW) continue;
            acc += g_local[(pb + sx)*1600 + rowbase + i*5 + j];
        }
    }
    long oidx = (((long)(b*HH + Y))*WW + X)*64 + c;
    outp[oidx] = gamma[0]*acc + x[oidx];
}

// =====================================================================
extern "C" void kernel_launch(void* const* d_in, const int* in_sizes, int n_in,
                              void* d_out, int out_size)
{
    const float* x     = (const float*)d_in[0];
    const float* Wq    = (const float*)d_in[1];
    const float* bq    = (const float*)d_in[2];
    const float* Wk    = (const float*)d_in[3];
    const float* bk    = (const float*)d_in[4];
    const float* Wv    = (const float*)d_in[5];
    const float* bv    = (const float*)d_in[6];
    const float* gamma = (const float*)d_in[7];

    float* outp     = (float*)d_out;
    float* attn_out = outp + (long)BATCH*HH*WW*CIN;   // out first, then attn

    cudaFuncSetAttribute(attn_kernel,
                         cudaFuncAttributeMaxDynamicSharedMemorySize, 91200);

    proj_kernel<<<BATCH*HH, 128>>>(x, Wq, bq, Wk, bk, Wv, bv);
    attn_kernel<<<BATCH*HH*(WW/NPX), 256, 91200>>>(attn_out);
    fold_kernel<<<BATCH*HH*(WW/NPX), 512>>>(x, gamma, outp);
}

// round 6
// speedup vs baseline: 1.0551x; 1.0551x over previous
#include <cuda_runtime.h>

#define BATCH 4
#define HH 128
#define WW 128
#define CIN 64
#define CQK 8
#define NPX 8          // pixels per attn block (consecutive x)
#define PLANE (HH*WW)

// ---------------- scratch (device globals, no runtime alloc) ----------------
__device__ float g_q[BATCH*CQK*PLANE];              //   2 MB
__device__ float g_k[BATCH*CQK*PLANE];              //   2 MB
__device__ float g_v[BATCH*CIN*PLANE];              //  16.8 MB
__device__ float g_partial[(long)BATCH*2048*3840];  // 125.8 MB fold partials

// =====================================================================
// Kernel A: 1x1-conv projections q,k,v  (NHWC input -> NCHW scratch)
// block = one image row (128 threads, thread = x), weights in smem
// =====================================================================
__global__ void proj_kernel(const float* __restrict__ x,
                            const float* __restrict__ Wq, const float* __restrict__ bq,
                            const float* __restrict__ Wk, const float* __restrict__ bk,
                            const float* __restrict__ Wv, const float* __restrict__ bv)
{
    __shared__ float s_wq[512], s_wk[512], s_wv[4096], s_bq[8], s_bk[8], s_bv[64];
    int tid = threadIdx.x;
    for (int i = tid; i < 512; i += 128) { s_wq[i] = Wq[i]; s_wk[i] = Wk[i]; }
    for (int i = tid; i < 4096; i += 128) s_wv[i] = Wv[i];
    if (tid < 8)  { s_bq[tid] = bq[tid]; s_bk[tid] = bk[tid]; }
    if (tid < 64) { s_bv[tid] = bv[tid]; }
    __syncthreads();

    int b = blockIdx.x >> 7;
    int y = blockIdx.x & 127;
    int xcol = tid;
    long pix = ((long)(b*HH + y))*WW + xcol;

    float xv[64];
    const float4* xp = (const float4*)(x + pix*64);
#pragma unroll
    for (int c4 = 0; c4 < 16; c4++) {
        float4 t = xp[c4];
        xv[c4*4+0] = t.x; xv[c4*4+1] = t.y; xv[c4*4+2] = t.z; xv[c4*4+3] = t.w;
    }

    int base_qk = (b*CQK)*PLANE + y*WW + xcol;
#pragma unroll 1
    for (int o = 0; o < 8; o++) {
        float aq = s_bq[o], ak = s_bk[o];
#pragma unroll
        for (int c = 0; c < 64; c++) {
            aq += xv[c]*s_wq[o*64+c];
            ak += xv[c]*s_wk[o*64+c];
        }
        g_q[base_qk + o*PLANE] = aq;
        g_k[base_qk + o*PLANE] = ak;
    }
    int base_v = (b*CIN)*PLANE + y*WW + xcol;
#pragma unroll 1
    for (int o = 0; o < 64; o++) {
        float av = s_bv[o];
#pragma unroll
        for (int c = 0; c < 64; c++) av += xv[c]*s_wv[o*64+c];
        g_v[base_v + o*PLANE] = av;
    }
}

// =====================================================================
// Kernel B: attention + block-level fold pre-reduction
// block = 8 consecutive x pixels, 256 threads
// dynamic smem (floats):
//   s_vp     [0, 12800)      per-pixel unfolded v  (vp[p][g])
//   s_att    [12800, 17800)  per-pixel logits/attn [p][625]
//   s_vt     [17800, 21640)  v halo tile [64][5][12]; REUSED as s_partial[5][12][64]
//   s_qt     [21640, 22120)  q halo tile [8][5][12]
//   s_kt     [22120, 22600)  k halo tile
//   s_off    [22600, 22800)  int LUT g<200 -> tile offset
//   s_chunk  [22800, 25360)  per-nb local chunk [8 px][320]
// total 25360 floats = 101440 B  (2 blocks/SM)
// =====================================================================
__global__ void __launch_bounds__(256, 2) attn_kernel(float* __restrict__ attn_out)
{
    extern __shared__ float sm[];
    float* s_vp   = sm;
    float* s_att  = sm + 12800;
    float* s_vt   = sm + 17800;   // later: s_partial
    float* s_qt   = sm + 21640;
    float* s_kt   = sm + 22120;
    int*   s_off  = (int*)(sm + 22600);
    float* s_chnk = sm + 22800;
    float* s_partial = s_vt;      // overlay (v tile dead after vp expansion)

    int tid = threadIdx.x;
    int b  = blockIdx.x >> 11;
    int r  = blockIdx.x & 2047;
    int y  = r >> 4;
    int x0 = (r & 15) * NPX;

    // ---- stage halo tiles (zero-padded like unfold) ----
    for (int idx = tid; idx < 480; idx += 256) {
        int c = idx/60, r2 = idx%60, dy = r2/12, xx = r2%12;
        int gy = y + dy - 2, gx = x0 + xx - 2;
        float vq = 0.f, vk = 0.f;
        if (gy >= 0 && gy < HH && gx >= 0 && gx < WW) {
            int gi = ((b*CQK + c)*HH + gy)*WW + gx;
            vq = g_q[gi]; vk = g_k[gi];
        }
        s_qt[idx] = vq; s_kt[idx] = vk;
    }
    for (int idx = tid; idx < 3840; idx += 256) {
        int ch = idx/60, r2 = idx%60, dy = r2/12, xx = r2%12;
        int gy = y + dy - 2, gx = x0 + xx - 2;
        float vv = 0.f;
        if (gy >= 0 && gy < HH && gx >= 0 && gx < WW)
            vv = g_v[((b*CIN + ch)*HH + gy)*WW + gx];
        s_vt[idx] = vv;
    }
    for (int g = tid; g < 200; g += 256) {
        int c = g/25, ko = g%25;
        s_off[g] = c*60 + (ko/5)*12 + (ko%5);
    }
    __syncthreads();

    // ---- expand v tile into per-pixel unfold-flat vectors ----
    for (int g = tid; g < 1600; g += 256) {
        int ch = g/25, ko = g%25;
        int off = ch*60 + (ko/5)*12 + (ko%5);
#pragma unroll
        for (int p = 0; p < NPX; p++) s_vp[p*1600 + g] = s_vt[off + p];
    }

    // ---- logits: qp[n,cc]·kp[m,cc] via offset LUT ----
    for (int idx = tid; idx < 5000; idx += 256) {
        int p = idx/625, e = idx - p*625;
        int n = e/25,    m = e - n*25;
        float acc = 0.f;
#pragma unroll
        for (int cc = 0; cc < 8; cc++)
            acc += s_qt[s_off[n*8+cc] + p] * s_kt[s_off[m*8+cc] + p];
        s_att[idx] = acc;
    }
    __syncthreads();   // also covers all vp-expansion reads of s_vt

    // ---- softmax over m (200 rows of 25) ----
    if (tid < 200) {
        int p = tid/25, n = tid - (tid/25)*25;
        float* row = s_att + p*625 + n*25;
        float mx = row[0];
#pragma unroll
        for (int m = 1; m < 25; m++) mx = fmaxf(mx, row[m]);
        float e_[25]; float sum = 0.f;
#pragma unroll
        for (int m = 0; m < 25; m++) { e_[m] = __expf(row[m]-mx); sum += e_[m]; }
        float inv = 1.f/sum;
#pragma unroll
        for (int m = 0; m < 25; m++) row[m] = e_[m]*inv;
    }
    __syncthreads();

    // ---- write attn out (vectorized, contiguous per block) ----
    long pixb = ((long)(b*HH + y))*WW + x0;
    {
        float4* ag = (float4*)(attn_out + pixb*625);
        const float4* as = (const float4*)s_att;
        for (int idx = tid; idx < 1250; idx += 256) ag[idx] = as[idx];
    }

    // ---- local (per nb chunk) + in-block fold reduction ----
    int p = tid >> 5, l = tid & 31;
    const float* vpp = s_vp + p*1600;
    const float* ap  = s_att + p*625;
#pragma unroll 1
    for (int nb = 0; nb < 5; nb++) {
        float a00=0,a01=0,a10=0,a11=0,a20=0,a21=0,a30=0,a31=0,a40=0,a41=0;
        const float* arow = ap + nb*125;
#pragma unroll 5
        for (int m = 0; m < 25; m++) {
            float v1 = vpp[m*64 + l];        // bank = lane: conflict-free
            float v2 = vpp[m*64 + 32 + l];
            float t0 = arow[m];        a00 += t0*v1; a01 += t0*v2;
            float t1 = arow[25 + m];   a10 += t1*v1; a11 += t1*v2;
            float t2 = arow[50 + m];   a20 += t2*v1; a21 += t2*v2;
            float t3 = arow[75 + m];   a30 += t3*v1; a31 += t3*v2;
            float t4 = arow[100 + m];  a40 += t4*v1; a41 += t4*v2;
        }
        float* o = s_chnk + p*320;
        o[l]     = a00; o[32+l]  = a01;
        o[64+l]  = a10; o[96+l]  = a11;
        o[128+l] = a20; o[160+l] = a21;
        o[192+l] = a30; o[224+l] = a31;
        o[256+l] = a40; o[288+l] = a41;
        __syncthreads();

        // fold 64 (c,dy) pairs of this chunk into s_partial[dy][tc][c]
        // pair q in [0,64): flat base = q*5, t = nb*64+q, c = t/5, dy = t%5
        int tbase = nb*64;
        for (int idx = tid; idx < 768; idx += 256) {
            int tc = idx >> 6;
            int q  = idx & 63;
            int t  = tbase + q;
            int c  = t/5;
            int dy = t - c*5;
            int bo = q*5;
            float acc = 0.f;
#pragma unroll
            for (int j = 0; j < 5; j++) {
                int pw = tc - j;
                if (pw >= 0 && pw < 8) acc += s_chnk[pw*320 + bo + j];
            }
            s_partial[dy*768 + tc*64 + c] = acc;
        }
        __syncthreads();
    }

    // ---- write fold partials (coalesced float4) ----
    {
        float4* gp = (float4*)(g_partial + (long)blockIdx.x*3840);
        const float4* ps = (const float4*)s_partial;
        for (int idx = tid; idx < 960; idx += 256) gp[idx] = ps[idx];
    }
}

// =====================================================================
// Kernel C: final fold = sum of <=10 partials per output + gamma*() + x
// block = 8 output pixels x 64 channels (512 threads, c fastest)
// =====================================================================
__global__ void fold_kernel(const float* __restrict__ x,
                            const float* __restrict__ gamma,
                            float* __restrict__ outp)
{
    int tid = threadIdx.x;
    int c  = tid & 63;
    int xi = tid >> 6;
    int b  = blockIdx.x >> 11;
    int r  = blockIdx.x & 2047;
    int Y  = r >> 4;
    int X  = (r & 15)*8 + xi;

    int xp2   = X + 2;
    int xb_hi = xp2 >> 3;          // tc in [0,8)
    int tc_hi = xp2 - (xb_hi<<3);
    int xb_lo = xb_hi - 1;         // tc in [8,12) if tc_hi < 4
    int tc_lo = tc_hi + 8;

    float acc = 0.f;
#pragma unroll
    for (int dy = 0; dy < 5; dy++) {
        int ys = Y + 2 - dy;
        if (ys < 0 || ys >= HH) continue;
        long rowb = ((long)(b*2048 + ys*16))*3840 + dy*768 + c;
        if (xb_hi < 16)
            acc += g_partial[rowb + (long)xb_hi*3840 + tc_hi*64];
        if (xb_lo >= 0 && tc_lo < 12)
            acc += g_partial[rowb + (long)xb_lo*3840 + tc_lo*64];
    }
    long oidx = (((long)(b*HH + Y))*WW + X)*64 + c;
    outp[oidx] = gamma[0]*acc + x[oidx];
}

// =====================================================================
extern "C" void kernel_launch(void* const* d_in, const int* in_sizes, int n_in,
                              void* d_out, int out_size)
{
    const float* x     = (const float*)d_in[0];
    const float* Wq    = (const float*)d_in[1];
    const float* bq    = (const float*)d_in[2];
    const float* Wk    = (const float*)d_in[3];
    const float* bk    = (const float*)d_in[4];
    const float* Wv    = (const float*)d_in[5];
    const float* bv    = (const float*)d_in[6];
    const float* gamma = (const float*)d_in[7];

    float* outp     = (float*)d_out;
    float* attn_out = outp + (long)BATCH*HH*WW*CIN;   // out first, then attn

    cudaFuncSetAttribute(attn_kernel,
                         cudaFuncAttributeMaxDynamicSharedMemorySize, 101440);

    proj_kernel<<<BATCH*HH, 128>>>(x, Wq, bq, Wk, bk, Wv, bv);
    attn_kernel<<<BATCH*HH*(WW/NPX), 256, 101440>>>(attn_out);
    fold_kernel<<<BATCH*HH*(WW/NPX), 512>>>(x, gamma, outp);
}

// round 7
// speedup vs baseline: 1.0810x; 1.0246x over previous
#include <cuda_runtime.h>

#define BATCH 4
#define HH 128
#define WW 128
#define CIN 64
#define CQK 8
#define NPX 8          // pixels per attn block (consecutive x)
#define PLANE (HH*WW)

// ---------------- scratch (device globals, no runtime alloc) ----------------
__device__ float g_q[BATCH*CQK*PLANE];              //   2 MB
__device__ float g_k[BATCH*CQK*PLANE];              //   2 MB
__device__ float g_v[BATCH*CIN*PLANE];              //  16.8 MB
__device__ float g_partial[(long)BATCH*2048*3840];  // 125.8 MB fold partials

// ---------------- f32x2 packed-math helpers ----------------
__device__ __forceinline__ unsigned long long pack2(float a, float b) {
    unsigned long long r;
    asm("mov.b64 %0, {%1,%2};" : "=l"(r) : "f"(a), "f"(b));
    return r;
}
__device__ __forceinline__ void unpack2(unsigned long long v, float& a, float& b) {
    asm("mov.b64 {%0,%1}, %2;" : "=f"(a), "=f"(b) : "l"(v));
}
__device__ __forceinline__ void fma2(unsigned long long& acc,
                                     unsigned long long a, unsigned long long b) {
    asm("fma.rn.f32x2 %0, %1, %2, %0;" : "+l"(acc) : "l"(a), "l"(b));
}

// =====================================================================
// Kernel A: 1x1-conv projections q,k,v  (NHWC input -> NCHW scratch)
// block = two image rows (256 threads)
// =====================================================================
__global__ void __launch_bounds__(256) proj_kernel(
                            const float* __restrict__ x,
                            const float* __restrict__ Wq, const float* __restrict__ bq,
                            const float* __restrict__ Wk, const float* __restrict__ bk,
                            const float* __restrict__ Wv, const float* __restrict__ bv)
{
    __shared__ float s_wq[512], s_wk[512], s_wv[4096], s_bq[8], s_bk[8], s_bv[64];
    int tid = threadIdx.x;
    for (int i = tid; i < 512; i += 256) { s_wq[i] = Wq[i]; s_wk[i] = Wk[i]; }
    for (int i = tid; i < 4096; i += 256) s_wv[i] = Wv[i];
    if (tid < 8)  { s_bq[tid] = bq[tid]; s_bk[tid] = bk[tid]; }
    if (tid < 64) { s_bv[tid] = bv[tid]; }
    __syncthreads();

    int rowpair = blockIdx.x;            // 0..255
    int b = rowpair >> 6;                // 64 row-pairs per batch
    int y = ((rowpair & 63) << 1) | (tid >> 7);
    int xcol = tid & 127;
    long pix = ((long)(b*HH + y))*WW + xcol;

    float xv[64];
    const float4* xp = (const float4*)(x + pix*64);
#pragma unroll
    for (int c4 = 0; c4 < 16; c4++) {
        float4 t = xp[c4];
        xv[c4*4+0] = t.x; xv[c4*4+1] = t.y; xv[c4*4+2] = t.z; xv[c4*4+3] = t.w;
    }

    int base_qk = (b*CQK)*PLANE + y*WW + xcol;
#pragma unroll 1
    for (int o = 0; o < 8; o++) {
        float aq = s_bq[o], ak = s_bk[o];
#pragma unroll
        for (int c = 0; c < 64; c++) {
            aq += xv[c]*s_wq[o*64+c];
            ak += xv[c]*s_wk[o*64+c];
        }
        g_q[base_qk + o*PLANE] = aq;
        g_k[base_qk + o*PLANE] = ak;
    }
    int base_v = (b*CIN)*PLANE + y*WW + xcol;
#pragma unroll 1
    for (int o = 0; o < 64; o++) {
        float av = s_bv[o];
#pragma unroll
        for (int c = 0; c < 64; c++) av += xv[c]*s_wv[o*64+c];
        g_v[base_v + o*PLANE] = av;
    }
}

// =====================================================================
// Kernel B: attention + block-level fold pre-reduction
// block = 8 consecutive x pixels, 256 threads (warp w = pixel w)
// dynamic smem (floats):
//   s_vp    [0, 12800)       per-pixel unfolded v vp[p][f], f = m*64+cc
//   s_att   [12800, 17800)   per-pixel attn [p][625]
//   s_vtp   [17800, 21640)   v halo tile [64][5][12]; REUSED as s_partial[5][12][64]
//   s_qt    [21640, 22120)   q halo tile [8][5][12]
//   s_kt    [22120, 22600)   k halo tile
//   s_chnk  [22600, 27720)   double-buffered local chunk 2 x [8 px][320]
// total 27720 floats = 110880 B  (2 blocks/SM)
// =====================================================================
__global__ void __launch_bounds__(256, 2) attn_kernel(float* __restrict__ attn_out)
{
    extern __shared__ float sm[];
    float* s_vp   = sm;
    float* s_att  = sm + 12800;
    float* s_vtp  = sm + 17800;   // later overlay: s_partial
    float* s_qt   = sm + 21640;
    float* s_kt   = sm + 22120;
    float* s_chnk = sm + 22600;   // 2 x 2560
    float* s_partial = s_vtp;

    int tid = threadIdx.x;
    int wid = tid >> 5;
    int l   = tid & 31;
    int b  = blockIdx.x >> 11;
    int r  = blockIdx.x & 2047;
    int y  = r >> 4;
    int x0 = (r & 15) * NPX;

    // ---- stage halo tiles (zero-padded like unfold) ----
    for (int idx = tid; idx < 480; idx += 256) {
        int c = idx/60, r2 = idx%60, dy = r2/12, xx = r2%12;
        int gy = y + dy - 2, gx = x0 + xx - 2;
        float vq = 0.f, vk = 0.f;
        if (gy >= 0 && gy < HH && gx >= 0 && gx < WW) {
            int gi = ((b*CQK + c)*HH + gy)*WW + gx;
            vq = g_q[gi]; vk = g_k[gi];
        }
        s_qt[idx] = vq; s_kt[idx] = vk;
    }
    for (int idx = tid; idx < 3840; idx += 256) {
        int ch = idx/60, r2 = idx%60, dy = r2/12, xx = r2%12;
        int gy = y + dy - 2, gx = x0 + xx - 2;
        float vv = 0.f;
        if (gy >= 0 && gy < HH && gx >= 0 && gx < WW)
            vv = g_v[((b*CIN + ch)*HH + gy)*WW + gx];
        s_vtp[idx] = vv;
    }
    __syncthreads();

    // ---- expand v tile into per-pixel unfold-flat vectors (f = m*64+cc) ----
    for (int g = tid; g < 1600; g += 256) {
        int ch = g/25, ko = g - ch*25;
        int off = ch*60 + (ko/5)*12 + (ko%5);
#pragma unroll
        for (int p = 0; p < NPX; p++) s_vp[p*1600 + g] = s_vtp[off + p];
    }

    // ---- logits + softmax, fully in-warp: warp wid owns pixel wid ----
    {
        int p = wid;
        float q_reg[8], k_reg[8];
#pragma unroll
        for (int cc = 0; cc < 8; cc++) {
            float vq = 0.f, vk = 0.f;
            if (l < 25) {
                int g  = l*8 + cc;           // flat index of (n=l, cc)
                int ch = g/25, ko = g - ch*25;
                int off = ch*60 + (ko/5)*12 + (ko%5) + p;
                vq = s_qt[off]; vk = s_kt[off];
            }
            q_reg[cc] = vq; k_reg[cc] = vk;
        }
#pragma unroll 1
        for (int n = 0; n < 25; n++) {
            float acc = 0.f;
#pragma unroll
            for (int cc = 0; cc < 8; cc++) {
                float qb = __shfl_sync(0xffffffffu, q_reg[cc], n);
                acc += qb * k_reg[cc];
            }
            float logit = (l < 25) ? acc : -3.0e38f;
            float mx = logit;
#pragma unroll
            for (int o = 16; o > 0; o >>= 1)
                mx = fmaxf(mx, __shfl_xor_sync(0xffffffffu, mx, o));
            float e = __expf(logit - mx);        // lanes >=25 -> 0
            float s = e;
#pragma unroll
            for (int o = 16; o > 0; o >>= 1)
                s += __shfl_xor_sync(0xffffffffu, s, o);
            float a = e * (1.0f / s);
            if (l < 25) s_att[p*625 + n*25 + l] = a;
        }
    }
    __syncthreads();   // s_att + s_vp ready; s_vtp dead -> becomes s_partial

    // ---- write attn out (vectorized, contiguous per block) ----
    long pixb = ((long)(b*HH + y))*WW + x0;
    {
        float4* ag = (float4*)(attn_out + pixb*625);
        const float4* as = (const float4*)s_att;
        for (int idx = tid; idx < 1250; idx += 256) ag[idx] = as[idx];
    }

    // ---- local (per nb chunk, f32x2 packed) + in-block fold reduction ----
    {
        int p = wid;
        const float* vpp = s_vp + p*1600 + 2*l;   // lane covers cc = 2l, 2l+1
        const float* ap  = s_att + p*625;
        int buf = 0;
#pragma unroll 1
        for (int nb = 0; nb < 5; nb++) {
            float av0 = 0.f, av1 = 0.f, av2 = 0.f, av3 = 0.f, av4 = 0.f;
            if (l < 25) {
                const float* arow = ap + nb*125 + l;
                av0 = arow[0]; av1 = arow[25]; av2 = arow[50];
                av3 = arow[75]; av4 = arow[100];
            }
            unsigned long long a0 = 0, a1 = 0, a2 = 0, a3 = 0, a4 = 0;
#pragma unroll
            for (int m = 0; m < 25; m++) {
                unsigned long long v2p = *(const unsigned long long*)(vpp + m*64);
                float t0 = __shfl_sync(0xffffffffu, av0, m);
                float t1 = __shfl_sync(0xffffffffu, av1, m);
                float t2 = __shfl_sync(0xffffffffu, av2, m);
                float t3 = __shfl_sync(0xffffffffu, av3, m);
                float t4 = __shfl_sync(0xffffffffu, av4, m);
                fma2(a0, pack2(t0, t0), v2p);
                fma2(a1, pack2(t1, t1), v2p);
                fma2(a2, pack2(t2, t2), v2p);
                fma2(a3, pack2(t3, t3), v2p);
                fma2(a4, pack2(t4, t4), v2p);
            }
            unsigned long long* o =
                (unsigned long long*)(s_chnk + buf*2560 + p*320 + 2*l);
            o[0]   = a0;   // row n=nb*5+0, cc 2l..2l+1
            o[32]  = a1;   // +64 floats
            o[64]  = a2;
            o[96]  = a3;
            o[128] = a4;
            __syncthreads();

            // fold 64 (c,dy) pairs of this chunk into s_partial[dy][tc][c]
            const float* ch = s_chnk + buf*2560;
            int tbase = nb*64;
            for (int idx = tid; idx < 768; idx += 256) {
                int tc = idx >> 6;
                int q  = idx & 63;
                int t  = tbase + q;
                int c  = t/5;
                int dy = t - c*5;
                int bo = q*5;
                float acc = 0.f;
#pragma unroll
                for (int j = 0; j < 5; j++) {
                    int pw = tc - j;
                    if (pw >= 0 && pw < 8) acc += ch[pw*320 + bo + j];
                }
                s_partial[dy*768 + tc*64 + c] = acc;
            }
            buf ^= 1;   // next chunk written into other buffer (safe past barrier)
        }
    }
    __syncthreads();

    // ---- write fold partials (coalesced float4) ----
    {
        float4* gp = (float4*)(g_partial + (long)blockIdx.x*3840);
        const float4* ps = (const float4*)s_partial;
        for (int idx = tid; idx < 960; idx += 256) gp[idx] = ps[idx];
    }
}

// =====================================================================
// Kernel C: final fold = sum of <=10 partials per output + gamma*() + x
// block = 8 output pixels x 64 channels (512 threads, c fastest)
// =====================================================================
__global__ void fold_kernel(const float* __restrict__ x,
                            const float* __restrict__ gamma,
                            float* __restrict__ outp)
{
    int tid = threadIdx.x;
    int c  = tid & 63;
    int xi = tid >> 6;
    int b  = blockIdx.x >> 11;
    int r  = blockIdx.x & 2047;
    int Y  = r >> 4;
    int X  = (r & 15)*8 + xi;

    int xp2   = X + 2;
    int xb_hi = xp2 >> 3;          // tc in [0,8)
    int tc_hi = xp2 - (xb_hi<<3);
    int xb_lo = xb_hi - 1;         // tc in [8,12) if tc_hi < 4
    int tc_lo = tc_hi + 8;

    float acc = 0.f;
#pragma unroll
    for (int dy = 0; dy < 5; dy++) {
        int ys = Y + 2 - dy;
        if (ys < 0 || ys >= HH) continue;
        long rowb = ((long)(b*2048 + ys*16))*3840 + dy*768 + c;
        if (xb_hi < 16)
            acc += g_partial[rowb + (long)xb_hi*3840 + tc_hi*64];
        if (xb_lo >= 0 && tc_lo < 12)
            acc += g_partial[rowb + (long)xb_lo*3840 + tc_lo*64];
    }
    long oidx = (((long)(b*HH + Y))*WW + X)*64 + c;
    outp[oidx] = gamma[0]*acc + x[oidx];
}

// =====================================================================
extern "C" void kernel_launch(void* const* d_in, const int* in_sizes, int n_in,
                              void* d_out, int out_size)
{
    const float* x     = (const float*)d_in[0];
    const float* Wq    = (const float*)d_in[1];
    const float* bq    = (const float*)d_in[2];
    const float* Wk    = (const float*)d_in[3];
    const float* bk    = (const float*)d_in[4];
    const float* Wv    = (const float*)d_in[5];
    const float* bv    = (const float*)d_in[6];
    const float* gamma = (const float*)d_in[7];

    float* outp     = (float*)d_out;
    float* attn_out = outp + (long)BATCH*HH*WW*CIN;   // out first, then attn

    cudaFuncSetAttribute(attn_kernel,
                         cudaFuncAttributeMaxDynamicSharedMemorySize, 110880);

    proj_kernel<<<BATCH*HH/2, 256>>>(x, Wq, bq, Wk, bk, Wv, bv);
    attn_kernel<<<BATCH*HH*(WW/NPX), 256, 110880>>>(attn_out);
    fold_kernel<<<BATCH*HH*(WW/NPX), 512>>>(x, gamma, outp);
}

// round 11
// speedup vs baseline: 1.6169x; 1.4957x over previous
#include <cuda_runtime.h>

#define BATCH 4
#define HH 128
#define WW 128
#define CIN 64
#define CQK 8
#define NPX 8          // pixels per attn block (consecutive x)
#define PLANE (HH*WW)
#define VSTRIDE 1664   // per-pixel v region: 13 x 128-float m-pair blocks

// ---------------- scratch (device globals, no runtime alloc) ----------------
__device__ float g_q[BATCH*CQK*PLANE];              //   2 MB
__device__ float g_k[BATCH*CQK*PLANE];              //   2 MB
__device__ float g_v[BATCH*CIN*PLANE];              //  16.8 MB
__device__ float g_partial[(long)BATCH*2048*3840];  // 125.8 MB fold partials

// =====================================================================
// Kernel A: 1x1-conv projections q,k,v  (NHWC input -> NCHW scratch)
// =====================================================================
__global__ void __launch_bounds__(256) proj_kernel(
                            const float* __restrict__ x,
                            const float* __restrict__ Wq, const float* __restrict__ bq,
                            const float* __restrict__ Wk, const float* __restrict__ bk,
                            const float* __restrict__ Wv, const float* __restrict__ bv)
{
    __shared__ float s_wq[512], s_wk[512], s_wv[4096], s_bq[8], s_bk[8], s_bv[64];
    int tid = threadIdx.x;
    for (int i = tid; i < 512; i += 256) { s_wq[i] = Wq[i]; s_wk[i] = Wk[i]; }
    for (int i = tid; i < 4096; i += 256) s_wv[i] = Wv[i];
    if (tid < 8)  { s_bq[tid] = bq[tid]; s_bk[tid] = bk[tid]; }
    if (tid < 64) { s_bv[tid] = bv[tid]; }
    __syncthreads();

    int rowpair = blockIdx.x;            // 0..255
    int b = rowpair >> 6;
    int y = ((rowpair & 63) << 1) | (tid >> 7);
    int xcol = tid & 127;
    long pix = ((long)(b*HH + y))*WW + xcol;

    float xv[64];
    const float4* xp = (const float4*)(x + pix*64);
#pragma unroll
    for (int c4 = 0; c4 < 16; c4++) {
        float4 t = xp[c4];
        xv[c4*4+0] = t.x; xv[c4*4+1] = t.y; xv[c4*4+2] = t.z; xv[c4*4+3] = t.w;
    }

    int base_qk = (b*CQK)*PLANE + y*WW + xcol;
#pragma unroll 1
    for (int o = 0; o < 8; o++) {
        float aq = s_bq[o], ak = s_bk[o];
#pragma unroll
        for (int c = 0; c < 64; c++) {
            aq += xv[c]*s_wq[o*64+c];
            ak += xv[c]*s_wk[o*64+c];
        }
        g_q[base_qk + o*PLANE] = aq;
        g_k[base_qk + o*PLANE] = ak;
    }
    int base_v = (b*CIN)*PLANE + y*WW + xcol;
#pragma unroll 1
    for (int o = 0; o < 64; o++) {
        float av = s_bv[o];
#pragma unroll
        for (int c = 0; c < 64; c++) av += xv[c]*s_wv[o*64+c];
        g_v[base_v + o*PLANE] = av;
    }
}

// =====================================================================
// Kernel B: attention + block-level fold pre-reduction
// block = 8 pixels, 256 threads, warp w = pixel w. 3 blocks/SM.
// smem (floats, total 18512 = 74048 B):
//   s_vp [0,13312): per-pixel v, stride VSTRIDE=1664, m-pair interleaved:
//                   perm(f) = (m>>1)*128 + (m&1)*2 + (cc>>1)*4 + (cc&1),
//                   f = m*64+cc;  region REUSED later as chunk[p][1600] flat
//   s_B  [13312,18512) = 5200-float union:
//        phase 1: v halo [64][5][12] @0, q halo @3840, k halo @4320
//        phase 2: s_att [8][25 rows, stride 26] (5200)
//        phase 3: s_partial[5][12][64] (3840)
// =====================================================================
__global__ void __launch_bounds__(256, 3) attn_kernel(float* __restrict__ attn_out)
{
    extern __shared__ float sm[];
    float* s_vp  = sm;
    float* s_B   = sm + NPX*VSTRIDE;   // 13312
    float* s_vt  = s_B;
    float* s_qt  = s_B + 3840;
    float* s_kt  = s_B + 4320;
    float* s_att = s_B;          // overlay after halo phase
    float* s_partial = s_B;      // overlay after attn export

    int tid = threadIdx.x;
    int wid = tid >> 5;
    int l   = tid & 31;
    int b  = blockIdx.x >> 11;
    int r  = blockIdx.x & 2047;
    int y  = r >> 4;
    int x0 = (r & 15) * NPX;
    int p  = wid;

    // ---- P0: stage halo tiles (zero-padded like unfold) ----
    for (int idx = tid; idx < 480; idx += 256) {
        int c = idx/60, r2 = idx%60, dy = r2/12, xx = r2%12;
        int gy = y + dy - 2, gx = x0 + xx - 2;
        float vq = 0.f, vk = 0.f;
        if (gy >= 0 && gy < HH && gx >= 0 && gx < WW) {
            int gi = ((b*CQK + c)*HH + gy)*WW + gx;
            vq = g_q[gi]; vk = g_k[gi];
        }
        s_qt[idx] = vq; s_kt[idx] = vk;
    }
    for (int idx = tid; idx < 3840; idx += 256) {
        int ch = idx/60, r2 = idx%60, dy = r2/12, xx = r2%12;
        int gy = y + dy - 2, gx = x0 + xx - 2;
        float vv = 0.f;
        if (gy >= 0 && gy < HH && gx >= 0 && gx < WW)
            vv = g_v[((b*CIN + ch)*HH + gy)*WW + gx];
        s_vt[idx] = vv;
    }
    __syncthreads();   // BAR1

    // ---- P1a: q/k rows -> registers (lane n = row n) ----
    float q_reg[8], k_reg[8];
#pragma unroll
    for (int cc = 0; cc < 8; cc++) {
        float vq = 0.f, vk = 0.f;
        if (l < 25) {
            int f  = l*8 + cc;
            int ch = f/25, ko = f - ch*25;
            int off = ch*60 + (ko/5)*12 + (ko%5) + p;
            vq = s_qt[off]; vk = s_kt[off];
        }
        q_reg[cc] = vq; k_reg[cc] = vk;
    }

    // ---- P1b: expand v tile -> per-pixel interleaved vectors ----
    for (int g = tid; g < 1600; g += 256) {
        int m  = g >> 6, cc = g & 63;
        int ch = g/25,  ko = g - (g/25)*25;
        int off  = ch*60 + (ko/5)*12 + (ko%5);
        int perm = (m>>1)*128 + (m&1)*2 + (cc>>1)*4 + (cc&1);
#pragma unroll
        for (int pp = 0; pp < NPX; pp++) s_vp[pp*VSTRIDE + perm] = s_vt[off + pp];
    }
    __syncthreads();   // BAR2 (halo reads done; s_B reusable)

    // ---- P2: logits + softmax, lane n owns full row n ----
    {
        float lg[25];
#pragma unroll
        for (int m = 0; m < 25; m++) {
            float acc = 0.f;
#pragma unroll
            for (int cc = 0; cc < 8; cc++)
                acc += q_reg[cc] * __shfl_sync(0xffffffffu, k_reg[cc], m);
            lg[m] = acc;
        }
        if (l < 25) {
            float mx = lg[0];
#pragma unroll
            for (int m = 1; m < 25; m++) mx = fmaxf(mx, lg[m]);
            float sum = 0.f;
#pragma unroll
            for (int m = 0; m < 25; m++) { lg[m] = __expf(lg[m] - mx); sum += lg[m]; }
            float inv = 1.0f / sum;
            float* row = s_att + p*650 + l*26;
#pragma unroll
            for (int m = 0; m < 25; m++) row[m] = lg[m]*inv;
        }
    }
    __syncthreads();   // BAR3

    // ---- P3a: export attn (compact from padded rows, coalesced STG) ----
    long pixb = ((long)(b*HH + y))*WW + x0;
    {
        float* ag = attn_out + pixb*625;
        for (int idx = tid; idx < 5000; idx += 256) {
            int pp = idx/625, e = idx - pp*625;
            int n = e/25, m = e - n*25;
            ag[idx] = s_att[pp*650 + n*26 + m];
        }
    }

    // ---- P3b: local = attn @ vp, all 25 n at once, m-paired ----
    {
        const float* sa = s_att + p*650;
        const float* vl = s_vp + p*VSTRIDE + 4*l;   // lane covers cc = 2l, 2l+1
        float a0[25], a1[25];
#pragma unroll
        for (int n = 0; n < 25; n++) { a0[n] = 0.f; a1[n] = 0.f; }
#pragma unroll
        for (int m2 = 0; m2 < 12; m2++) {
            float4 v = *(const float4*)(vl + m2*128);
            // v.x=(m even,cc2l) v.y=(m even,cc2l+1) v.z=(m odd,cc2l) v.w=(m odd,cc2l+1)
#pragma unroll
            for (int n = 0; n < 25; n++) {
                float2 t = *(const float2*)(sa + n*26 + 2*m2);   // broadcast LDS.64
                a0[n] += t.x*v.x + t.y*v.z;
                a1[n] += t.x*v.y + t.y*v.w;
            }
        }
        {   // tail m = 24 (block 12 of the interleaved layout)
            float2 v24 = *(const float2*)(vl + 1536);
#pragma unroll
            for (int n = 0; n < 25; n++) {
                float t = sa[n*26 + 24];
                a0[n] += t*v24.x;
                a1[n] += t*v24.y;
            }
        }
        // store chunk (flat layout f = n*64+cc) over own s_vp region
        float* ck = s_vp + p*VSTRIDE;
#pragma unroll
        for (int n = 0; n < 25; n++)
            *(float2*)(ck + n*64 + 2*l) = make_float2(a0[n], a1[n]);
    }
    __syncthreads();   // BAR4 (chunks visible; s_att reads done)

    // ---- P4: in-block fold reduction: chunk -> s_partial[dy][tc][c] ----
    for (int idx = tid; idx < 3840; idx += 256) {
        int nb  = idx/768;
        int rem = idx - nb*768;
        int tc  = rem >> 6;
        int q   = rem & 63;
        int t   = nb*64 + q;
        int c   = t/5;
        int dy  = t - c*5;
        int f0  = 5*t;
        float acc = 0.f;
#pragma unroll
        for (int j = 0; j < 5; j++) {
            int pw = tc - j;
            if (pw >= 0 && pw < 8) acc += s_vp[pw*VSTRIDE + f0 + j];
        }
        s_partial[dy*768 + tc*64 + c] = acc;
    }
    __syncthreads();   // BAR5

    // ---- P5: write fold partials (coalesced float4) ----
    {
        float4* gp = (float4*)(g_partial + (long)blockIdx.x*3840);
        const float4* ps = (const float4*)s_partial;
        for (int idx = tid; idx < 960; idx += 256) gp[idx] = ps[idx];
    }
}

// =====================================================================
// Kernel C: final fold = sum of <=10 partials per output + gamma*() + x
// =====================================================================
__global__ void fold_kernel(const float* __restrict__ x,
                            const float* __restrict__ gamma,
                            float* __restrict__ outp)
{
    int tid = threadIdx.x;
    int c  = tid & 63;
    int xi = tid >> 6;
    int b  = blockIdx.x >> 11;
    int r  = blockIdx.x & 2047;
    int Y  = r >> 4;
    int X  = (r & 15)*8 + xi;

    int xp2   = X + 2;
    int xb_hi = xp2 >> 3;          // tc in [0,8)
    int tc_hi = xp2 - (xb_hi<<3);
    int xb_lo = xb_hi - 1;         // tc in [8,12) if tc_hi < 4
    int tc_lo = tc_hi + 8;

    float acc = 0.f;
#pragma unroll
    for (int dy = 0; dy < 5; dy++) {
        int ys = Y + 2 - dy;
        if (ys < 0 || ys >= HH) continue;
        long rowb = ((long)(b*2048 + ys*16))*3840 + dy*768 + c;
        if (xb_hi < 16)
            acc += g_partial[rowb + (long)xb_hi*3840 + tc_hi*64];
        if (xb_lo >= 0 && tc_lo < 12)
            acc += g_partial[rowb + (long)xb_lo*3840 + tc_lo*64];
    }
    long oidx = (((long)(b*HH + Y))*WW + X)*64 + c;
    outp[oidx] = gamma[0]*acc + x[oidx];
}

// =====================================================================
extern "C" void kernel_launch(void* const* d_in, const int* in_sizes, int n_in,
                              void* d_out, int out_size)
{
    const float* x     = (const float*)d_in[0];
    const float* Wq    = (const float*)d_in[1];
    const float* bq    = (const float*)d_in[2];
    const float* Wk    = (const float*)d_in[3];
    const float* bk    = (const float*)d_in[4];
    const float* Wv    = (const float*)d_in[5];
    const float* bv    = (const float*)d_in[6];
    const float* gamma = (const float*)d_in[7];

    float* outp     = (float*)d_out;
    float* attn_out = outp + (long)BATCH*HH*WW*CIN;   // out first, then attn

    cudaFuncSetAttribute(attn_kernel,
                         cudaFuncAttributeMaxDynamicSharedMemorySize, 74048);

    proj_kernel<<<BATCH*HH/2, 256>>>(x, Wq, bq, Wk, bk, Wv, bv);
    attn_kernel<<<BATCH*HH*(WW/NPX), 256, 74048>>>(attn_out);
    fold_kernel<<<BATCH*HH*(WW/NPX), 512>>>(x, gamma, outp);
}

// round 12
// speedup vs baseline: 1.6803x; 1.0392x over previous
#include <cuda_runtime.h>

#define BATCH 4
#define HH 128
#define WW 128
#define CIN 64
#define CQK 8
#define NPX 8          // pixels per attn block (consecutive x)
#define PLANE (HH*WW)
#define VSTRIDE 1664   // per-pixel v region: 13 x 128-float m-pair blocks
#define ASTRIDE 28     // attn row stride (16B-aligned float4 reads)
#define APIX (25*ASTRIDE)   // 700 floats per pixel

// ---------------- scratch (device globals, no runtime alloc) ----------------
__device__ float g_q[BATCH*CQK*PLANE];              //   2 MB
__device__ float g_k[BATCH*CQK*PLANE];              //   2 MB
__device__ float g_v[BATCH*CIN*PLANE];              //  16.8 MB
__device__ float g_partial[(long)BATCH*2048*3840];  // 125.8 MB fold partials

// =====================================================================
// Kernel A: 1x1-conv projections q,k,v  (NHWC input -> NCHW scratch)
// float4-vectorized weight loads (4x fewer LDS issues)
// =====================================================================
__global__ void __launch_bounds__(256) proj_kernel(
                            const float* __restrict__ x,
                            const float* __restrict__ Wq, const float* __restrict__ bq,
                            const float* __restrict__ Wk, const float* __restrict__ bk,
                            const float* __restrict__ Wv, const float* __restrict__ bv)
{
    __shared__ float s_wq[512], s_wk[512], s_wv[4096], s_bq[8], s_bk[8], s_bv[64];
    int tid = threadIdx.x;
    for (int i = tid; i < 512; i += 256) { s_wq[i] = Wq[i]; s_wk[i] = Wk[i]; }
    for (int i = tid; i < 4096; i += 256) s_wv[i] = Wv[i];
    if (tid < 8)  { s_bq[tid] = bq[tid]; s_bk[tid] = bk[tid]; }
    if (tid < 64) { s_bv[tid] = bv[tid]; }
    __syncthreads();

    int rowpair = blockIdx.x;            // 0..255
    int b = rowpair >> 6;
    int y = ((rowpair & 63) << 1) | (tid >> 7);
    int xcol = tid & 127;
    long pix = ((long)(b*HH + y))*WW + xcol;

    float4 xv[16];
    const float4* xp = (const float4*)(x + pix*64);
#pragma unroll
    for (int c4 = 0; c4 < 16; c4++) xv[c4] = xp[c4];

    int base_qk = (b*CQK)*PLANE + y*WW + xcol;
#pragma unroll 1
    for (int o = 0; o < 8; o++) {
        float aq = s_bq[o], ak = s_bk[o];
        const float4* wq4 = (const float4*)(s_wq + o*64);
        const float4* wk4 = (const float4*)(s_wk + o*64);
#pragma unroll
        for (int c4 = 0; c4 < 16; c4++) {
            float4 wq = wq4[c4], wk = wk4[c4], xc = xv[c4];
            aq += xc.x*wq.x + xc.y*wq.y + xc.z*wq.z + xc.w*wq.w;
            ak += xc.x*wk.x + xc.y*wk.y + xc.z*wk.z + xc.w*wk.w;
        }
        g_q[base_qk + o*PLANE] = aq;
        g_k[base_qk + o*PLANE] = ak;
    }
    int base_v = (b*CIN)*PLANE + y*WW + xcol;
#pragma unroll 1
    for (int o = 0; o < 64; o++) {
        float av = s_bv[o];
        const float4* wv4 = (const float4*)(s_wv + o*64);
#pragma unroll
        for (int c4 = 0; c4 < 16; c4++) {
            float4 wv = wv4[c4], xc = xv[c4];
            av += xc.x*wv.x + xc.y*wv.y + xc.z*wv.z + xc.w*wv.w;
        }
        g_v[base_v + o*PLANE] = av;
    }
}

// =====================================================================
// Kernel B: attention + block-level fold pre-reduction
// block = 8 pixels, 256 threads, warp w = pixel w. 3 blocks/SM.
// smem (floats, total 18912 = 75648 B):
//   s_vp [0,13312): per-pixel v, stride VSTRIDE=1664, m-pair interleaved:
//                   perm(f) = (m>>1)*128 + (m&1)*2 + (cc>>1)*4 + (cc&1),
//                   f = m*64+cc;  region REUSED later as chunk[p][1600] flat
//   s_B  [13312,18912) = 5600-float union:
//        phase 1: v halo [64][5][12] @0, q halo @3840, k halo @4320
//        phase 2: s_att [8][25 rows, stride 28] (5600)
//        phase 3: s_partial[5][12][64] (3840)
// =====================================================================
__global__ void __launch_bounds__(256, 3) attn_kernel(float* __restrict__ attn_out)
{
    extern __shared__ float sm[];
    float* s_vp  = sm;
    float* s_B   = sm + NPX*VSTRIDE;   // 13312
    float* s_vt  = s_B;
    float* s_qt  = s_B + 3840;
    float* s_kt  = s_B + 4320;
    float* s_att = s_B;          // overlay after halo phase
    float* s_partial = s_B;      // overlay after attn export

    int tid = threadIdx.x;
    int wid = tid >> 5;
    int l   = tid & 31;
    int b  = blockIdx.x >> 11;
    int r  = blockIdx.x & 2047;
    int y  = r >> 4;
    int x0 = (r & 15) * NPX;
    int p  = wid;

    // ---- P0: stage halo tiles (zero-padded like unfold) ----
    for (int idx = tid; idx < 480; idx += 256) {
        int c = idx/60, r2 = idx%60, dy = r2/12, xx = r2%12;
        int gy = y + dy - 2, gx = x0 + xx - 2;
        float vq = 0.f, vk = 0.f;
        if (gy >= 0 && gy < HH && gx >= 0 && gx < WW) {
            int gi = ((b*CQK + c)*HH + gy)*WW + gx;
            vq = g_q[gi]; vk = g_k[gi];
        }
        s_qt[idx] = vq; s_kt[idx] = vk;
    }
    for (int idx = tid; idx < 3840; idx += 256) {
        int ch = idx/60, r2 = idx%60, dy = r2/12, xx = r2%12;
        int gy = y + dy - 2, gx = x0 + xx - 2;
        float vv = 0.f;
        if (gy >= 0 && gy < HH && gx >= 0 && gx < WW)
            vv = g_v[((b*CIN + ch)*HH + gy)*WW + gx];
        s_vt[idx] = vv;
    }
    __syncthreads();   // BAR1

    // ---- P1a: q/k rows -> registers (lane n = row n) ----
    float q_reg[8], k_reg[8];
#pragma unroll
    for (int cc = 0; cc < 8; cc++) {
        float vq = 0.f, vk = 0.f;
        if (l < 25) {
            int f  = l*8 + cc;
            int ch = f/25, ko = f - ch*25;
            int off = ch*60 + (ko/5)*12 + (ko%5) + p;
            vq = s_qt[off]; vk = s_kt[off];
        }
        q_reg[cc] = vq; k_reg[cc] = vk;
    }

    // ---- P1b: expand v tile -> per-pixel interleaved vectors ----
    for (int g = tid; g < 1600; g += 256) {
        int m  = g >> 6, cc = g & 63;
        int ch = g/25,  ko = g - (g/25)*25;
        int off  = ch*60 + (ko/5)*12 + (ko%5);
        int perm = (m>>1)*128 + (m&1)*2 + (cc>>1)*4 + (cc&1);
#pragma unroll
        for (int pp = 0; pp < NPX; pp++) s_vp[pp*VSTRIDE + perm] = s_vt[off + pp];
    }
    __syncthreads();   // BAR2 (halo reads done; s_B reusable)

    // ---- P2: logits + softmax, lane n owns full row n ----
    {
        float lg[25];
#pragma unroll
        for (int m = 0; m < 25; m++) {
            float acc = 0.f;
#pragma unroll
            for (int cc = 0; cc < 8; cc++)
                acc += q_reg[cc] * __shfl_sync(0xffffffffu, k_reg[cc], m);
            lg[m] = acc;
        }
        if (l < 25) {
            float mx = lg[0];
#pragma unroll
            for (int m = 1; m < 25; m++) mx = fmaxf(mx, lg[m]);
            float sum = 0.f;
#pragma unroll
            for (int m = 0; m < 25; m++) { lg[m] = __expf(lg[m] - mx); sum += lg[m]; }
            float inv = 1.0f / sum;
            float* row = s_att + p*APIX + l*ASTRIDE;
#pragma unroll
            for (int m = 0; m < 25; m++) row[m] = lg[m]*inv;
        }
    }
    __syncthreads();   // BAR3

    // ---- P3a: export attn (compact from padded rows, coalesced STG) ----
    long pixb = ((long)(b*HH + y))*WW + x0;
    {
        float* ag = attn_out + pixb*625;
        for (int idx = tid; idx < 5000; idx += 256) {
            int pp = idx/625, e = idx - pp*625;
            int n = e/25, m = e - n*25;
            ag[idx] = s_att[pp*APIX + n*ASTRIDE + m];
        }
    }

    // ---- P3b: local = attn @ vp, quad-m inner steps ----
    {
        const float* sa = s_att + p*APIX;
        const float* vl = s_vp + p*VSTRIDE + 4*l;   // lane covers cc = 2l, 2l+1
        float a0[25], a1[25];
#pragma unroll
        for (int n = 0; n < 25; n++) { a0[n] = 0.f; a1[n] = 0.f; }
#pragma unroll
        for (int j = 0; j < 6; j++) {               // m = 4j .. 4j+3
            float4 v0 = *(const float4*)(vl + (2*j)*128);
            float4 v1 = *(const float4*)(vl + (2*j+1)*128);
            // v0.x=(4j,c0) v0.y=(4j,c1) v0.z=(4j+1,c0) v0.w=(4j+1,c1)
            // v1.x=(4j+2,c0) ... v1.w=(4j+3,c1)
#pragma unroll
            for (int n = 0; n < 25; n++) {
                float4 t = *(const float4*)(sa + n*ASTRIDE + 4*j);  // broadcast LDS.128
                a0[n] += t.x*v0.x + t.y*v0.z + t.z*v1.x + t.w*v1.z;
                a1[n] += t.x*v0.y + t.y*v0.w + t.z*v1.y + t.w*v1.w;
            }
        }
        {   // tail m = 24 (block 12 of the interleaved layout)
            float2 v24 = *(const float2*)(vl + 1536);
#pragma unroll
            for (int n = 0; n < 25; n++) {
                float t = sa[n*ASTRIDE + 24];
                a0[n] += t*v24.x;
                a1[n] += t*v24.y;
            }
        }
        // store chunk (flat layout f = n*64+cc) over own s_vp region
        float* ck = s_vp + p*VSTRIDE;
#pragma unroll
        for (int n = 0; n < 25; n++)
            *(float2*)(ck + n*64 + 2*l) = make_float2(a0[n], a1[n]);
    }
    __syncthreads();   // BAR4 (chunks visible; s_att reads done)

    // ---- P4: in-block fold reduction: chunk -> s_partial[dy][tc][c] ----
    for (int idx = tid; idx < 3840; idx += 256) {
        int nb  = idx/768;
        int rem = idx - nb*768;
        int tc  = rem >> 6;
        int q   = rem & 63;
        int t   = nb*64 + q;
        int c   = t/5;
        int dy  = t - c*5;
        int f0  = 5*t;
        float acc = 0.f;
#pragma unroll
        for (int j = 0; j < 5; j++) {
            int pw = tc - j;
            if (pw >= 0 && pw < 8) acc += s_vp[pw*VSTRIDE + f0 + j];
        }
        s_partial[dy*768 + tc*64 + c] = acc;
    }
    __syncthreads();   // BAR5

    // ---- P5: write fold partials (coalesced float4) ----
    {
        float4* gp = (float4*)(g_partial + (long)blockIdx.x*3840);
        const float4* ps = (const float4*)s_partial;
        for (int idx = tid; idx < 960; idx += 256) gp[idx] = ps[idx];
    }
}

// =====================================================================
// Kernel C: final fold = sum of <=10 partials per output + gamma*() + x
// =====================================================================
__global__ void fold_kernel(const float* __restrict__ x,
                            const float* __restrict__ gamma,
                            float* __restrict__ outp)
{
    int tid = threadIdx.x;
    int c  = tid & 63;
    int xi = tid >> 6;
    int b  = blockIdx.x >> 11;
    int r  = blockIdx.x & 2047;
    int Y  = r >> 4;
    int X  = (r & 15)*8 + xi;

    int xp2   = X + 2;
    int xb_hi = xp2 >> 3;          // tc in [0,8)
    int tc_hi = xp2 - (xb_hi<<3);
    int xb_lo = xb_hi - 1;         // tc in [8,12) if tc_hi < 4
    int tc_lo = tc_hi + 8;

    float acc = 0.f;
#pragma unroll
    for (int dy = 0; dy < 5; dy++) {
        int ys = Y + 2 - dy;
        if (ys < 0 || ys >= HH) continue;
        long rowb = ((long)(b*2048 + ys*16))*3840 + dy*768 + c;
        if (xb_hi < 16)
            acc += g_partial[rowb + (long)xb_hi*3840 + tc_hi*64];
        if (xb_lo >= 0 && tc_lo < 12)
            acc += g_partial[rowb + (long)xb_lo*3840 + tc_lo*64];
    }
    long oidx = (((long)(b*HH + Y))*WW + X)*64 + c;
    outp[oidx] = gamma[0]*acc + x[oidx];
}

// =====================================================================
extern "C" void kernel_launch(void* const* d_in, const int* in_sizes, int n_in,
                              void* d_out, int out_size)
{
    const float* x     = (const float*)d_in[0];
    const float* Wq    = (const float*)d_in[1];
    const float* bq    = (const float*)d_in[2];
    const float* Wk    = (const float*)d_in[3];
    const float* bk    = (const float*)d_in[4];
    const float* Wv    = (const float*)d_in[5];
    const float* bv    = (const float*)d_in[6];
    const float* gamma = (const float*)d_in[7];

    float* outp     = (float*)d_out;
    float* attn_out = outp + (long)BATCH*HH*WW*CIN;   // out first, then attn

    cudaFuncSetAttribute(attn_kernel,
                         cudaFuncAttributeMaxDynamicSharedMemorySize, 75648);

    proj_kernel<<<BATCH*HH/2, 256>>>(x, Wq, bq, Wk, bk, Wv, bv);
    attn_kernel<<<BATCH*HH*(WW/NPX), 256, 75648>>>(attn_out);
    fold_kernel<<<BATCH*HH*(WW/NPX), 512>>>(x, gamma, outp);
}